// round 3
// baseline (speedup 1.0000x reference)
#include <cuda_runtime.h>

#define NQ      8
#define KCODES  1024
#define DIM     64
#define TOKENS  65536
#define CHUNK   64
#define CTA_THREADS 64

typedef unsigned long long u64;

// per-stage codebook squared norms, bit-exact sequential order
__device__ float g_csq[NQ * KCODES];

// packed fp32x2 FMA: acc = a*b + acc  (each lane = exact scalar fma.rn)
__device__ __forceinline__ void ffma2(u64& acc, u64 a, u64 b) {
    asm("fma.rn.f32x2 %0, %1, %2, %0;" : "+l"(acc) : "l"(a), "l"(b));
}
__device__ __forceinline__ u64 dup2(float v) {
    u64 r;
    asm("mov.b64 %0, {%1, %1};" : "=l"(r) : "f"(v));
    return r;
}
__device__ __forceinline__ void unpack2(float& lo, float& hi, u64 v) {
    asm("mov.b64 {%0, %1}, %2;" : "=f"(lo), "=f"(hi) : "l"(v));
}

// c_sq[k] = sequential d-ascending: acc = fadd(acc, fmul(c,c))  (no fma)
__global__ void csq_kernel(const float* __restrict__ cb) {
    int r = blockIdx.x * blockDim.x + threadIdx.x;   // 0 .. NQ*KCODES-1
    const float4* row = reinterpret_cast<const float4*>(cb + (size_t)r * DIM);
    float s = 0.f;
#pragma unroll
    for (int i = 0; i < DIM / 4; i++) {
        float4 v = row[i];
        s = __fadd_rn(s, __fmul_rn(v.x, v.x));
        s = __fadd_rn(s, __fmul_rn(v.y, v.y));
        s = __fadd_rn(s, __fmul_rn(v.z, v.z));
        s = __fadd_rn(s, __fmul_rn(v.w, v.w));
    }
    g_csq[r] = s;
}

__global__ void __launch_bounds__(CTA_THREADS, 8)
rvq_kernel(const float* __restrict__ x,
           const float* __restrict__ cb,
           float* __restrict__ out) {
    // transposed tile: smT[d][k] so adjacent codes pack into one u64
    __shared__ float smT[DIM][CHUNK];
    __shared__ float scq[CHUNK];

    const int tid   = threadIdx.x;
    const int token = blockIdx.x * CTA_THREADS + tid;

    // residual as 64 scalar fp32 registers
    float r[DIM];
    {
        const float4* xr = reinterpret_cast<const float4*>(x + (size_t)token * DIM);
#pragma unroll
        for (int p = 0; p < DIM / 4; p++) {
            float4 v = xr[p];
            r[4 * p]     = v.x;
            r[4 * p + 1] = v.y;
            r[4 * p + 2] = v.z;
            r[4 * p + 3] = v.w;
        }
    }

#pragma unroll 1
    for (int q = 0; q < NQ; q++) {
        const float* cbq = cb + (size_t)q * KCODES * DIM;

        // r_sq: sequential d-ascending, fadd(fmul), no contraction
        float rsq = 0.f;
#pragma unroll
        for (int d = 0; d < DIM; d++)
            rsq = __fadd_rn(rsq, __fmul_rn(r[d], r[d]));

        float best = __int_as_float(0x7f800000);   // +inf
        int   bk   = 0;

#pragma unroll 1
        for (int c = 0; c < KCODES / CHUNK; c++) {
            __syncthreads();
            // thread tid loads code row (c*64+tid), writes transposed column
            {
                const float4* src = reinterpret_cast<const float4*>(
                    cbq + (size_t)(c * CHUNK + tid) * DIM);
#pragma unroll
                for (int i = 0; i < DIM / 4; i++) {
                    float4 v = src[i];
                    smT[4 * i][tid]     = v.x;
                    smT[4 * i + 1][tid] = v.y;
                    smT[4 * i + 2][tid] = v.z;
                    smT[4 * i + 3][tid] = v.w;
                }
                scq[tid] = g_csq[q * KCODES + c * CHUNK + tid];
            }
            __syncthreads();

            // two 32-code blocks; each code's dot = sequential d-ascending fma chain
#pragma unroll 1
            for (int g = 0; g < CHUNK; g += 32) {
                u64 acc[16];
#pragma unroll
                for (int j = 0; j < 16; j++) acc[j] = 0ull;

#pragma unroll 8
                for (int d = 0; d < DIM; d++) {
                    u64 rd2 = dup2(r[d]);
                    const ulonglong2* row =
                        reinterpret_cast<const ulonglong2*>(&smT[d][g]);
#pragma unroll
                    for (int m = 0; m < 8; m++) {
                        ulonglong2 cv = row[m];    // LDS.128 broadcast
                        ffma2(acc[2 * m],     rd2, cv.x);
                        ffma2(acc[2 * m + 1], rd2, cv.y);
                    }
                }

                // dist = (r_sq - 2*dot) + c_sq, exact reference op order
#pragma unroll
                for (int j = 0; j < 16; j++) {
                    float d0, d1;
                    unpack2(d0, d1, acc[j]);
                    int k0 = c * CHUNK + g + 2 * j;
                    float s0 = __fadd_rn(__fsub_rn(rsq, __fmul_rn(2.0f, d0)),
                                         scq[g + 2 * j]);
                    float s1 = __fadd_rn(__fsub_rn(rsq, __fmul_rn(2.0f, d1)),
                                         scq[g + 2 * j + 1]);
                    if (s0 < best) { best = s0; bk = k0; }
                    if (s1 < best) { best = s1; bk = k0 + 1; }
                }
            }
        }

        // residual -= codebook[bk], single rounding per element (matches ref)
        {
            const float4* crow = reinterpret_cast<const float4*>(
                cbq + (size_t)bk * DIM);
#pragma unroll
            for (int p = 0; p < DIM / 4; p++) {
                float4 v = crow[p];
                r[4 * p]     = __fsub_rn(r[4 * p],     v.x);
                r[4 * p + 1] = __fsub_rn(r[4 * p + 1], v.y);
                r[4 * p + 2] = __fsub_rn(r[4 * p + 2], v.z);
                r[4 * p + 3] = __fsub_rn(r[4 * p + 3], v.w);
            }
        }
    }

    // out = x - residual_final  (ulp-equal to reference's accumulated qout)
    {
        const float4* xr = reinterpret_cast<const float4*>(x + (size_t)token * DIM);
        float4* orow = reinterpret_cast<float4*>(out + (size_t)token * DIM);
#pragma unroll
        for (int p = 0; p < DIM / 4; p++) {
            float4 v = xr[p];
            v.x = __fsub_rn(v.x, r[4 * p]);
            v.y = __fsub_rn(v.y, r[4 * p + 1]);
            v.z = __fsub_rn(v.z, r[4 * p + 2]);
            v.w = __fsub_rn(v.w, r[4 * p + 3]);
            orow[p] = v;
        }
    }
}

extern "C" void kernel_launch(void* const* d_in, const int* in_sizes, int n_in,
                              void* d_out, int out_size) {
    const float* x;
    const float* cb;
    if (in_sizes[0] == NQ * KCODES * DIM) {
        cb = (const float*)d_in[0];
        x  = (const float*)d_in[1];
    } else {
        x  = (const float*)d_in[0];
        cb = (const float*)d_in[1];
    }
    float* out = (float*)d_out;

    csq_kernel<<<(NQ * KCODES) / 128, 128>>>(cb);
    rvq_kernel<<<TOKENS / CTA_THREADS, CTA_THREADS>>>(x, cb, out);
}